// round 12
// baseline (speedup 1.0000x reference)
#include <cuda_runtime.h>
#include <cuda_bf16.h>
#include <cstdint>

// GrahamLoss: 3-kernel S/T pipeline.
// A: S=bf16(F+D), T=bf16(D-F) -> gmem scratch (HBM-bound stream).
// B: M = S T^T per batch, 128x128 tiles (16/batch x 16 = 256 uniform CTAs),
//    bf16 mma.sync with 32x64 warp tiles, cp.async 3-stage pipeline.
// C: loss = sum_b sum_{r,c} ((M_rc + M_cr)/2)^2 / 2^40  (64x64 pair blocks,
//    upper triangle, deterministic last-CTA reduction).

#define B_    16
#define C_    512
#define HW_   1024
#define NELT  ((size_t)B_ * C_ * HW_)   // 8388608
#define KC    64             // bf16 k per chunk
#define NCH   (HW_ / KC)     // 16
#define NT2   36
#define NPART (B_ * NT2)     // 576

// kernel B smem: 3 stages x (S panel 16KB + T panel 16KB)
#define OS  0
#define OT  16384
#define STG 32768
#define DYN_SMEM (3 * STG)   // 96 KB

__device__ __align__(16) __nv_bfloat16 g_S[NELT];    // 16.7 MB
__device__ __align__(16) __nv_bfloat16 g_T[NELT];    // 16.7 MB
__device__ float        g_M[(size_t)B_ * C_ * C_];   // 16.8 MB
__device__ float        g_partials[NPART];
__device__ unsigned int g_count;

__constant__ int c_u[NT2] = {0,0,0,0,0,0,0,0,1,1,1,1,1,1,1,2,2,2,2,2,2,3,3,3,3,3,4,4,4,4,5,5,5,6,6,7};
__constant__ int c_v[NT2] = {0,1,2,3,4,5,6,7,1,2,3,4,5,6,7,2,3,4,5,6,7,3,4,5,6,7,4,5,6,7,5,6,7,6,7,7};

// ---------- helpers ----------
__device__ __forceinline__ uint32_t smem_u32(const void* p) {
    uint32_t a;
    asm("{ .reg .u64 t; cvta.to.shared.u64 t, %1; cvt.u32.u64 %0, t; }" : "=r"(a) : "l"(p));
    return a;
}
// 128B-row panel address, bf16 col k in [0,64): 16B unit XOR row&7 (conflict-free)
__device__ __forceinline__ uint32_t paddr(uint32_t pbase, int row, int k) {
    return pbase + (uint32_t)row * 128u
         + ((((uint32_t)(k >> 3) ^ (uint32_t)row) & 7u) << 4) + ((uint32_t)(k & 7) << 1);
}
__device__ __forceinline__ uint32_t pack2(float hi, float lo) {
    uint32_t r;
    asm("cvt.rn.bf16x2.f32 %0, %1, %2;" : "=r"(r) : "f"(hi), "f"(lo));
    return r;
}
__device__ __forceinline__ void cp_async16(uint32_t dst, const void* src) {
    asm volatile("cp.async.cg.shared.global [%0], [%1], 16;" :: "r"(dst), "l"(src) : "memory");
}
__device__ __forceinline__ void cp_commit() { asm volatile("cp.async.commit_group;" ::: "memory"); }
template <int N>
__device__ __forceinline__ void cp_wait() { asm volatile("cp.async.wait_group %0;" :: "n"(N) : "memory"); }
__device__ __forceinline__ void ldm_x4(uint32_t* r, uint32_t addr) {
    asm volatile("ldmatrix.sync.aligned.m8n8.x4.shared.b16 {%0,%1,%2,%3}, [%4];"
                 : "=r"(r[0]), "=r"(r[1]), "=r"(r[2]), "=r"(r[3]) : "r"(addr));
}
__device__ __forceinline__ void mma_bf16(float* d, const uint32_t* a, const uint32_t* b) {
    asm volatile("mma.sync.aligned.m16n8k16.row.col.f32.bf16.bf16.f32 "
                 "{%0,%1,%2,%3}, {%4,%5,%6,%7}, {%8,%9}, {%0,%1,%2,%3};"
                 : "+f"(d[0]), "+f"(d[1]), "+f"(d[2]), "+f"(d[3])
                 : "r"(a[0]), "r"(a[1]), "r"(a[2]), "r"(a[3]), "r"(b[0]), "r"(b[1]));
}

// ---------- kernel A: S/T conversion ----------
__global__ __launch_bounds__(256)
void st_convert_kernel(const float* __restrict__ F, const float* __restrict__ Dm) {
    const size_t base = (size_t)blockIdx.x * 256 + threadIdx.x;
    const float4* F4 = (const float4*)F;
    const float4* D4 = (const float4*)Dm;
    uint2* S2 = (uint2*)g_S;
    uint2* T2 = (uint2*)g_T;
    #pragma unroll
    for (int k = 0; k < 8; k++) {
        size_t i = base + (size_t)k * 262144;   // 1024 blocks * 256 threads
        float4 f = F4[i];
        float4 d = D4[i];
        S2[i] = make_uint2(pack2(f.y + d.y, f.x + d.x), pack2(f.w + d.w, f.z + d.z));
        T2[i] = make_uint2(pack2(d.y - f.y, d.x - f.x), pack2(d.w - f.w, d.z - f.z));
    }
}

// ---------- kernel B: M = S T^T, 128x128 tiles ----------
__global__ __launch_bounds__(256, 2)
void gram_m_kernel() {
    extern __shared__ __align__(128) unsigned char smem[];

    const int tid  = threadIdx.x;
    const int lane = tid & 31;
    const int wid  = tid >> 5;
    const int b    = blockIdx.y;
    const int I    = blockIdx.x >> 2;
    const int J    = blockIdx.x & 3;

    const __nv_bfloat16* SIg = g_S + ((size_t)b * C_ + I * 128) * HW_;
    const __nv_bfloat16* TJg = g_T + ((size_t)b * C_ + J * 128) * HW_;

    const uint32_t sbase = smem_u32(smem);

    // warp tiling: 4(m) x 2(n) warps, warp tile 32 x 64
    const int wm = wid >> 1;
    const int wn = wid & 1;
    const int arow0 = wm * 32;
    const int brow0 = wn * 64;

    // producer: slot = tid + j*256 (j<4) -> row = slot>>3 (0..127), u = slot&7
    const int prow = tid >> 3;   // +32 per j
    const int pu   = tid & 7;

    float acc[2][8][4];
    #pragma unroll
    for (int mt = 0; mt < 2; mt++)
        #pragma unroll
        for (int nt = 0; nt < 8; nt++)
            #pragma unroll
            for (int r = 0; r < 4; r++) acc[mt][nt][r] = 0.f;

    auto issue = [&](int c) {
        const uint32_t stg = sbase + (uint32_t)(c % 3) * STG;
        const int kb = c * KC;
        #pragma unroll
        for (int j = 0; j < 4; j++) {
            int row = prow + j * 32;
            uint32_t so = (uint32_t)row * 128u + ((((uint32_t)pu ^ (uint32_t)row) & 7u) << 4);
            size_t gb = (size_t)row * HW_ + kb + pu * 8;
            cp_async16(stg + OS + so, SIg + gb);
            cp_async16(stg + OT + so, TJg + gb);
        }
        cp_commit();
    };

    issue(0);
    issue(1);

    const int a_row = lane & 15;
    const int a_k   = (lane >> 4) << 3;
    const int b_row = (((lane >> 4) & 1) << 3) + (lane & 7);
    const int b_k   = ((lane >> 3) & 1) << 3;

    for (int c = 0; c < NCH; c++) {
        if (c == NCH - 1) cp_wait<0>(); else cp_wait<1>();
        __syncthreads();
        if (c + 2 < NCH) issue(c + 2);

        const uint32_t stb = sbase + (uint32_t)(c % 3) * STG;
        const uint32_t pS = stb + OS;
        const uint32_t pT = stb + OT;

        #pragma unroll
        for (int ks = 0; ks < 4; ks++) {
            const int k0 = ks * 16;
            uint32_t af[2][4], bf[8][2];
            ldm_x4(af[0], paddr(pS, arow0 + a_row,      k0 + a_k));
            ldm_x4(af[1], paddr(pS, arow0 + 16 + a_row, k0 + a_k));
            #pragma unroll
            for (int tp = 0; tp < 4; tp++) {
                uint32_t t4[4];
                ldm_x4(t4, paddr(pT, brow0 + tp * 16 + b_row, k0 + b_k));
                bf[2 * tp][0] = t4[0]; bf[2 * tp][1] = t4[1];
                bf[2 * tp + 1][0] = t4[2]; bf[2 * tp + 1][1] = t4[3];
            }
            #pragma unroll
            for (int mt = 0; mt < 2; mt++)
                #pragma unroll
                for (int nt = 0; nt < 8; nt++)
                    mma_bf16(acc[mt][nt], af[mt], bf[nt]);
        }
        __syncthreads();
    }

    // write M tile
    const int quad = lane >> 2;
    const int tcol = (lane & 3) * 2;
    float* Mb = g_M + ((size_t)b << 18);   // b * 512 * 512
    #pragma unroll
    for (int mt = 0; mt < 2; mt++) {
        #pragma unroll
        for (int nt = 0; nt < 8; nt++) {
            int r_ = I * 128 + arow0 + mt * 16 + quad;
            int c_ = J * 128 + brow0 + nt * 8 + tcol;
            float* p = Mb + (size_t)r_ * C_ + c_;
            *(float2*)p            = make_float2(acc[mt][nt][0], acc[mt][nt][1]);
            *(float2*)(p + 8 * C_) = make_float2(acc[mt][nt][2], acc[mt][nt][3]);
        }
    }
}

// ---------- kernel C: loss = sum ((M + M^T)/2)^2 / 2^40 ----------
__global__ __launch_bounds__(256)
void pair_reduce_kernel(float* __restrict__ out) {
    __shared__ float sB[64][65];
    __shared__ float red[256];
    __shared__ unsigned int s_islast;

    const int tid = threadIdx.x;
    const int b   = blockIdx.y;
    const int u = c_u[blockIdx.x];
    const int v = c_v[blockIdx.x];
    const float* Mb = g_M + ((size_t)b << 18);

    // stage sB = M[v-block rows, u-block cols]
    #pragma unroll
    for (int i = 0; i < 16; i++) {
        int idx = tid + i * 256;
        int r = idx >> 6, cc = idx & 63;
        sB[r][cc] = Mb[(size_t)(v * 64 + r) * C_ + u * 64 + cc];
    }
    __syncthreads();

    float local = 0.f;
    const int r  = tid >> 2;
    const int cs = (tid & 3) * 16;
    const float* arow = Mb + (size_t)(u * 64 + r) * C_ + v * 64 + cs;
    if (u < v) {
        // entries (r,c) and mirrored (c,r): 2*s^2 with s=(a+bT)/2 => 0.5*(a+bT)^2
        #pragma unroll
        for (int i = 0; i < 16; i++) {
            float sum = arow[i] + sB[cs + i][r];
            local = fmaf(0.5f * sum, sum, local);
        }
    } else {
        #pragma unroll
        for (int i = 0; i < 16; i++) {
            int c = cs + i;
            float a = arow[i];
            if (c > r) {
                float sum = a + sB[c][r];
                local = fmaf(0.5f * sum, sum, local);
            } else if (c == r) {
                local = fmaf(a, a, local);
            }
        }
    }

    red[tid] = local;
    __syncthreads();
    #pragma unroll
    for (int stp = 128; stp > 0; stp >>= 1) {
        if (tid < stp) red[tid] += red[tid + stp];
        __syncthreads();
    }

    if (tid == 0) {
        g_partials[b * NT2 + blockIdx.x] = red[0];
        __threadfence();
        unsigned int prev = atomicAdd(&g_count, 1u);
        s_islast = (prev == NPART - 1) ? 1u : 0u;
    }
    __syncthreads();
    if (s_islast) {
        __threadfence();
        float vsum = 0.f;
        for (int i = tid; i < NPART; i += 256) vsum += g_partials[i];
        red[tid] = vsum;
        __syncthreads();
        #pragma unroll
        for (int stp = 128; stp > 0; stp >>= 1) {
            if (tid < stp) red[tid] += red[tid + stp];
            __syncthreads();
        }
        if (tid == 0) {
            out[0] = red[0] * (1.0f / 1099511627776.0f);  // / 2^40
            g_count = 0;  // reset for next graph replay
        }
    }
}

extern "C" void kernel_launch(void* const* d_in, const int* in_sizes, int n_in,
                              void* d_out, int out_size) {
    const float* F = (const float*)d_in[0];   // feat
    const float* D = (const float*)d_in[1];   // feat_decod
    float* out = (float*)d_out;

    cudaFuncSetAttribute(gram_m_kernel, cudaFuncAttributeMaxDynamicSharedMemorySize, DYN_SMEM);
    st_convert_kernel<<<1024, 256>>>(F, D);
    dim3 gB(16, B_);
    gram_m_kernel<<<gB, 256, DYN_SMEM>>>();
    dim3 gC(NT2, B_);
    pair_reduce_kernel<<<gC, 256>>>(out);
}

// round 14
// speedup vs baseline: 1.0735x; 1.0735x over previous
#include <cuda_runtime.h>
#include <cuda_bf16.h>
#include <cstdint>

// GrahamLoss: 2-kernel S/T pipeline, split-K pair-tile gram.
// A: S=bf16(F+D), T=bf16(D-F) -> gmem scratch (HBM-bound).
// B: per 64x64 pair-tile (I<=J, 8x8 grid, x16 batches = 576 CTAs):
//    warp-pairs compute {P k-half0, Q k-half0, P k-half1, Q k-half1} with
//    32x64 warp tiles (P=S_I T_J^T, Q=S_J T_I^T); diag: 4-way split-K on P.
//    Pair P with Q^T in smem, square, weight, reduce; last CTA finalizes.

#define B_    16
#define C_    512
#define HW_   1024
#define NELT  ((size_t)B_ * C_ * HW_)   // 8388608
#define KC    64             // bf16 k per chunk
#define NCH   (HW_ / KC)     // 16
#define NT2   36
#define NPART (B_ * NT2)     // 576

// kernel B smem: 3 stages x 32KB (4 panels x 8KB: 64 rows x 128B swizzled)
#define OSI 0
#define OTI 8192
#define OSJ 16384
#define OTJ 24576
#define STG 32768
#define DYN_SMEM (3 * STG)   // 96 KB
#define EPW 65               // epilogue buffer row stride (floats)

__device__ __align__(16) __nv_bfloat16 g_S[NELT];   // 16.7 MB
__device__ __align__(16) __nv_bfloat16 g_T[NELT];   // 16.7 MB
__device__ float        g_partials[NPART];
__device__ unsigned int g_count;

__constant__ int c_u[NT2] = {0,0,0,0,0,0,0,0,1,1,1,1,1,1,1,2,2,2,2,2,2,3,3,3,3,3,4,4,4,4,5,5,5,6,6,7};
__constant__ int c_v[NT2] = {0,1,2,3,4,5,6,7,1,2,3,4,5,6,7,2,3,4,5,6,7,3,4,5,6,7,4,5,6,7,5,6,7,6,7,7};

// ---------- helpers ----------
__device__ __forceinline__ uint32_t smem_u32(const void* p) {
    uint32_t a;
    asm("{ .reg .u64 t; cvta.to.shared.u64 t, %1; cvt.u32.u64 %0, t; }" : "=r"(a) : "l"(p));
    return a;
}
// 128B-row panel address, bf16 col k in [0,64): 16B unit XOR row&7 (conflict-free)
__device__ __forceinline__ uint32_t paddr(uint32_t pbase, int row, int k) {
    return pbase + (uint32_t)row * 128u
         + ((((uint32_t)(k >> 3) ^ (uint32_t)row) & 7u) << 4) + ((uint32_t)(k & 7) << 1);
}
__device__ __forceinline__ uint32_t pack2(float hi, float lo) {
    uint32_t r;
    asm("cvt.rn.bf16x2.f32 %0, %1, %2;" : "=r"(r) : "f"(hi), "f"(lo));
    return r;
}
__device__ __forceinline__ void cp_async16(uint32_t dst, const void* src) {
    asm volatile("cp.async.cg.shared.global [%0], [%1], 16;" :: "r"(dst), "l"(src) : "memory");
}
__device__ __forceinline__ void cp_commit() { asm volatile("cp.async.commit_group;" ::: "memory"); }
template <int N>
__device__ __forceinline__ void cp_wait() { asm volatile("cp.async.wait_group %0;" :: "n"(N) : "memory"); }
__device__ __forceinline__ void ldm_x4(uint32_t* r, uint32_t addr) {
    asm volatile("ldmatrix.sync.aligned.m8n8.x4.shared.b16 {%0,%1,%2,%3}, [%4];"
                 : "=r"(r[0]), "=r"(r[1]), "=r"(r[2]), "=r"(r[3]) : "r"(addr));
}
__device__ __forceinline__ void mma_bf16(float* d, const uint32_t* a, const uint32_t* b) {
    asm volatile("mma.sync.aligned.m16n8k16.row.col.f32.bf16.bf16.f32 "
                 "{%0,%1,%2,%3}, {%4,%5,%6,%7}, {%8,%9}, {%0,%1,%2,%3};"
                 : "+f"(d[0]), "+f"(d[1]), "+f"(d[2]), "+f"(d[3])
                 : "r"(a[0]), "r"(a[1]), "r"(a[2]), "r"(a[3]), "r"(b[0]), "r"(b[1]));
}

struct Frag { uint32_t a[2][4]; uint32_t b[8][2]; };   // 32x64 warp tile, one k16

__device__ __forceinline__ void ld_fr(uint32_t pA, int arow0, uint32_t pB,
                                      int k0, int lane, Frag& f) {
    const int a_row = lane & 15;
    const int a_k   = (lane >> 4) << 3;
    ldm_x4(f.a[0], paddr(pA, arow0 + a_row,      k0 + a_k));
    ldm_x4(f.a[1], paddr(pA, arow0 + 16 + a_row, k0 + a_k));
    const int b_row = (((lane >> 4) & 1) << 3) + (lane & 7);
    const int b_k   = ((lane >> 3) & 1) << 3;
    #pragma unroll
    for (int tp = 0; tp < 4; tp++) {
        uint32_t t4[4];
        ldm_x4(t4, paddr(pB, tp * 16 + b_row, k0 + b_k));
        f.b[2 * tp][0] = t4[0]; f.b[2 * tp][1] = t4[1];
        f.b[2 * tp + 1][0] = t4[2]; f.b[2 * tp + 1][1] = t4[3];
    }
}
__device__ __forceinline__ void mma_fr(float acc[2][8][4], const Frag& f) {
    #pragma unroll
    for (int mt = 0; mt < 2; mt++)
        #pragma unroll
        for (int nt = 0; nt < 8; nt++)
            mma_bf16(acc[mt][nt], f.a[mt], f.b[nt]);
}

// ---------- kernel A: S/T conversion ----------
__global__ __launch_bounds__(256)
void st_convert_kernel(const float* __restrict__ F, const float* __restrict__ Dm) {
    const size_t base = (size_t)blockIdx.x * 256 + threadIdx.x;
    const float4* F4 = (const float4*)F;
    const float4* D4 = (const float4*)Dm;
    uint2* S2 = (uint2*)g_S;
    uint2* T2 = (uint2*)g_T;
    #pragma unroll
    for (int k = 0; k < 8; k++) {
        size_t i = base + (size_t)k * 262144;   // 1024 blocks * 256 threads
        float4 f = F4[i];
        float4 d = D4[i];
        S2[i] = make_uint2(pack2(f.y + d.y, f.x + d.x), pack2(f.w + d.w, f.z + d.z));
        T2[i] = make_uint2(pack2(d.y - f.y, d.x - f.x), pack2(d.w - f.w, d.z - f.z));
    }
}

// ---------- kernel B: pair-tile gram, split-K ----------
__global__ __launch_bounds__(256, 2)
void gram_st_kernel(float* __restrict__ out) {
    extern __shared__ __align__(128) unsigned char smem[];
    __shared__ float red[256];
    __shared__ unsigned int s_islast;

    const int tid  = threadIdx.x;
    const int lane = tid & 31;
    const int wid  = tid >> 5;
    const int b    = blockIdx.y;
    const int I = c_u[blockIdx.x];
    const int J = c_v[blockIdx.x];
    const int diag = (I == J);
    const float w = diag ? 1.0f : 2.0f;

    const __nv_bfloat16* SIg = g_S + ((size_t)b * C_ + I * 64) * HW_;
    const __nv_bfloat16* TIg = g_T + ((size_t)b * C_ + I * 64) * HW_;
    const __nv_bfloat16* SJg = g_S + ((size_t)b * C_ + J * 64) * HW_;
    const __nv_bfloat16* TJg = g_T + ((size_t)b * C_ + J * 64) * HW_;

    const uint32_t sbase = smem_u32(smem);

    // warp layout: bufid = wid>>1 (epilogue buffer), arow0 = (wid&1)*32
    // non-diag: bufid = {P k-half0, Q k-half0, P k-half1, Q k-half1}
    // diag:     bufid = P k-quarter bufid
    const int bufid = wid >> 1;
    const int arow0 = (wid & 1) * 32;
    uint32_t oA, oB;
    int ks0, nks;
    if (diag) { oA = OSI; oB = OTI; ks0 = bufid; nks = 1; }
    else {
        int role = bufid & 1, kg = bufid >> 1;
        oA = role ? OSJ : OSI;     // P: A=S_I ; Q: A=S_J
        oB = role ? OTI : OTJ;     // P: B=T_J ; Q: B=T_I
        ks0 = kg * 2; nks = 2;
    }

    // producer: slot = tid + j*256 (j<2) -> row = slot>>3 (0..63), u = slot&7
    const int prow = tid >> 3;
    const int pu   = tid & 7;
    const uint32_t pso = (uint32_t)prow * 128u + ((((uint32_t)pu ^ (uint32_t)prow) & 7u) << 4);
    const uint32_t pso2 = (uint32_t)(prow + 32) * 128u
                        + ((((uint32_t)pu ^ (uint32_t)(prow + 32)) & 7u) << 4);
    const size_t pgb  = (size_t)prow * HW_ + pu * 8;
    const size_t pgb2 = (size_t)(prow + 32) * HW_ + pu * 8;

    float acc[2][8][4];
    #pragma unroll
    for (int mt = 0; mt < 2; mt++)
        #pragma unroll
        for (int nt = 0; nt < 8; nt++)
            #pragma unroll
            for (int r = 0; r < 4; r++) acc[mt][nt][r] = 0.f;

    // prologue: chunks 0,1
    #pragma unroll
    for (int c0 = 0; c0 < 2; c0++) {
        const uint32_t stg = sbase + (uint32_t)c0 * STG;
        const int kb = c0 * KC;
        cp_async16(stg + OSI + pso,  SIg + pgb  + kb);
        cp_async16(stg + OTI + pso,  TIg + pgb  + kb);
        cp_async16(stg + OSI + pso2, SIg + pgb2 + kb);
        cp_async16(stg + OTI + pso2, TIg + pgb2 + kb);
        if (!diag) {
            cp_async16(stg + OSJ + pso,  SJg + pgb  + kb);
            cp_async16(stg + OTJ + pso,  TJg + pgb  + kb);
            cp_async16(stg + OSJ + pso2, SJg + pgb2 + kb);
            cp_async16(stg + OTJ + pso2, TJg + pgb2 + kb);
        }
        cp_commit();
    }

    for (int c = 0; c < NCH; c++) {
        if (c == NCH - 1) cp_wait<0>(); else cp_wait<1>();
        __syncthreads();
        if (c + 2 < NCH) {
            const int cn = c + 2;
            const uint32_t stg = sbase + (uint32_t)(cn % 3) * STG;
            const int kb = cn * KC;
            cp_async16(stg + OSI + pso,  SIg + pgb  + kb);
            cp_async16(stg + OTI + pso,  TIg + pgb  + kb);
            cp_async16(stg + OSI + pso2, SIg + pgb2 + kb);
            cp_async16(stg + OTI + pso2, TIg + pgb2 + kb);
            if (!diag) {
                cp_async16(stg + OSJ + pso,  SJg + pgb  + kb);
                cp_async16(stg + OTJ + pso,  TJg + pgb  + kb);
                cp_async16(stg + OSJ + pso2, SJg + pgb2 + kb);
                cp_async16(stg + OTJ + pso2, TJg + pgb2 + kb);
            }
            cp_commit();
        }

        const uint32_t stb = sbase + (uint32_t)(c % 3) * STG;
        const uint32_t pA = stb + oA;
        const uint32_t pB = stb + oB;

        Frag f0;
        ld_fr(pA, arow0, pB, ks0 * 16, lane, f0);
        if (nks == 2) {
            Frag f1;
            ld_fr(pA, arow0, pB, (ks0 + 1) * 16, lane, f1);
            mma_fr(acc, f0);
            mma_fr(acc, f1);
        } else {
            mma_fr(acc, f0);
        }
    }
    __syncthreads();   // all stages consumed; smem reusable

    // ---- epilogue: 4 partial buffers, pair P with Q^T ----
    float* sBuf = (float*)smem;                 // 4 x (64 x EPW) = 66560 B
    {
        float* dst = sBuf + bufid * (64 * EPW);
        const int quad = lane >> 2;
        const int tcol = (lane & 3) * 2;
        #pragma unroll
        for (int mt = 0; mt < 2; mt++) {
            #pragma unroll
            for (int nt = 0; nt < 8; nt++) {
                int r0 = arow0 + mt * 16 + quad;
                int c0 = nt * 8 + tcol;
                dst[r0 * EPW + c0]             = acc[mt][nt][0];
                dst[r0 * EPW + c0 + 1]         = acc[mt][nt][1];
                dst[(r0 + 8) * EPW + c0]       = acc[mt][nt][2];
                dst[(r0 + 8) * EPW + c0 + 1]   = acc[mt][nt][3];
            }
        }
    }
    __syncthreads();

    const float* B0 = sBuf;
    const float* B1 = sBuf + 1 * (64 * EPW);
    const float* B2 = sBuf + 2 * (64 * EPW);
    const float* B3 = sBuf + 3 * (64 * EPW);
    float local = 0.f;
    #pragma unroll
    for (int i = 0; i < 16; i++) {
        int e = tid + i * 256;
        int r = e >> 6, cc = e & 63;
        float p, q;
        if (diag) {
            p = (B0[r * EPW + cc] + B1[r * EPW + cc]) + (B2[r * EPW + cc] + B3[r * EPW + cc]);
            q = (B0[cc * EPW + r] + B1[cc * EPW + r]) + (B2[cc * EPW + r] + B3[cc * EPW + r]);
        } else {
            p = B0[r * EPW + cc] + B2[r * EPW + cc];
            q = B1[cc * EPW + r] + B3[cc * EPW + r];
        }
        float val = 0.5f * (p + q);
        local = fmaf(val, val, local);
    }
    local *= w;

    red[tid] = local;
    __syncthreads();
    #pragma unroll
    for (int stp = 128; stp > 0; stp >>= 1) {
        if (tid < stp) red[tid] += red[tid + stp];
        __syncthreads();
    }

    if (tid == 0) {
        g_partials[b * NT2 + blockIdx.x] = red[0];
        __threadfence();
        unsigned int prev = atomicAdd(&g_count, 1u);
        s_islast = (prev == NPART - 1) ? 1u : 0u;
    }
    __syncthreads();
    if (s_islast) {
        __threadfence();
        float v = 0.f;
        for (int i = tid; i < NPART; i += 256) v += g_partials[i];
        red[tid] = v;
        __syncthreads();
        #pragma unroll
        for (int stp = 128; stp > 0; stp >>= 1) {
            if (tid < stp) red[tid] += red[tid + stp];
            __syncthreads();
        }
        if (tid == 0) {
            out[0] = red[0] * (1.0f / 1099511627776.0f);  // / 2^40
            g_count = 0;  // reset for next graph replay
        }
    }
}

extern "C" void kernel_launch(void* const* d_in, const int* in_sizes, int n_in,
                              void* d_out, int out_size) {
    const float* F = (const float*)d_in[0];   // feat
    const float* D = (const float*)d_in[1];   // feat_decod
    float* out = (float*)d_out;

    cudaFuncSetAttribute(gram_st_kernel, cudaFuncAttributeMaxDynamicSharedMemorySize, DYN_SMEM);
    st_convert_kernel<<<1024, 256>>>(F, D);
    dim3 grid(NT2, B_);
    gram_st_kernel<<<grid, 256, DYN_SMEM>>>(out);
}